// round 13
// baseline (speedup 1.0000x reference)
#include <cuda_runtime.h>
#include <cuda_fp16.h>
#include <cstdint>
#include <math.h>

#define BB 4
#define NQ 4096
#define NKV 4096
#define CC 128
#define FF 128
#define BN 128
#define NT (NKV / BN)
#define REG 16384            // 64-col half-region (128 rows x 128B)
#define TPADB 272            // flash: padded row pitch (bytes), conflict-free ldmatrix
#define TILE_B (128 * TPADB) // 34816 B per staged tile
#define OPITCH 132           // epilogue smem float pitch
#define QSCALE 0.127518749639422f  // log2(e)/sqrt(128)

// fp16 operands (device globals: allocation-free rule)
__device__ __half g_K[BB * NKV * FF];   // [b,m,f]
__device__ __half g_VT[BB * FF * NKV];  // [b,f,m]
__device__ __half g_WT[3 * CC * FF];    // Wq^T, Wk^T, Wv^T fp16 [f][c]

// ---------------------------------------------------------------------------
__device__ __forceinline__ uint32_t smem_u32(const void* p) {
  uint32_t a;
  asm("{ .reg .u64 t; cvta.to.shared.u64 t, %1; cvt.u32.u64 %0, t; }" : "=r"(a) : "l"(p));
  return a;
}
__device__ __forceinline__ uint32_t swz(uint32_t r, uint32_t cb) {
  return r * 128u + (cb ^ ((r & 7u) << 4));
}
__device__ __forceinline__ float ex2f(float x) {
  float y;
  asm("ex2.approx.f32 %0, %1;" : "=f"(y) : "f"(x));
  return y;
}

#define LDSM_X4(bb, addr)                                                      \
  asm volatile("ldmatrix.sync.aligned.m8n8.x4.shared.b16 {%0,%1,%2,%3}, [%4];" \
               : "=r"((bb)[0]), "=r"((bb)[1]), "=r"((bb)[2]), "=r"((bb)[3])    \
               : "r"(addr))

__device__ __forceinline__ void mma16816(float c[4], const uint32_t a[4],
                                         const uint32_t b[2]) {
  asm volatile(
      "mma.sync.aligned.m16n8k16.row.col.f32.f16.f16.f32 "
      "{%0,%1,%2,%3}, {%4,%5,%6,%7}, {%8,%9}, {%0,%1,%2,%3};"
      : "+f"(c[0]), "+f"(c[1]), "+f"(c[2]), "+f"(c[3])
      : "r"(a[0]), "r"(a[1]), "r"(a[2]), "r"(a[3]), "r"(b[0]), "r"(b[1]));
}

#define CP_COMMIT() asm volatile("cp.async.commit_group;" ::: "memory")
#define CP_WAIT1() asm volatile("cp.async.wait_group 1;" ::: "memory")
#define CP_WAIT0() asm volatile("cp.async.wait_group 0;" ::: "memory")
#define CP16(dst, src) \
  asm volatile("cp.async.ca.shared.global [%0], [%1], 16;" ::"r"(dst), "l"(src) : "memory")

// flash staging: 128x128 fp16 tile into TPADB-padded smem (256 threads)
__device__ __forceinline__ void stage_async(const __half* __restrict__ g,
                                            size_t gstride, char* s, int t) {
  uint32_t sb = smem_u32(s);
#pragma unroll
  for (int i = 0; i < 8; ++i) {
    int idx = t + i * 256;
    int r = idx >> 4, c = idx & 15;
    uint32_t dst = sb + r * TPADB + c * 16;
    CP16(dst, (const void*)(g + (size_t)r * gstride + c * 8));
  }
}

// 128x128 fp16 tile into 2 swizzled 16KB regions
template <int NTH>
__device__ __forceinline__ void stage_tile_swz(const __half* __restrict__ g,
                                               size_t gstride, uint32_t sb, int t) {
#pragma unroll
  for (int i = 0; i < 2048 / NTH; ++i) {
    int idx = t + i * NTH;
    uint32_t r = idx >> 4, c = idx & 15;
    uint32_t dst = sb + (c >> 3) * REG + swz(r, (c & 7) * 16);
    CP16(dst, (const void*)(g + (size_t)r * gstride + c * 8));
  }
}

// 128x128 fp32 -> fp16 tile into 2 swizzled regions (direct stores)
template <int NTH>
__device__ __forceinline__ void stage_x_fp16(const float* __restrict__ X,
                                             char* sX, int t) {
#pragma unroll
  for (int i = 0; i < 4096 / NTH; ++i) {
    int idx = t + i * NTH;
    uint32_t r = idx >> 5, cq = idx & 31;
    float4 v = *(const float4*)(X + (size_t)r * CC + cq * 4);
    __half2 h0 = __floats2half2_rn(v.x, v.y);
    __half2 h1 = __floats2half2_rn(v.z, v.w);
    uint32_t fb = cq * 8;
    uint32_t off = (fb >> 7) * REG + swz(r, fb & 127);
    *(uint2*)(sX + off) = make_uint2(*(uint32_t*)&h0, *(uint32_t*)&h1);
  }
}

// ===========================================================================
// prep: W fp32 [c][f] -> WT fp16 [f][c]  (coalesced both ways via smem)
// ===========================================================================
__global__ __launch_bounds__(256) void prep_wt(const float* __restrict__ Wq,
                                               const float* __restrict__ Wk,
                                               const float* __restrict__ Wv,
                                               __half* __restrict__ WT) {
  extern __shared__ float sw[];  // 128 x 129
  const float* W = blockIdx.x == 0 ? Wq : (blockIdx.x == 1 ? Wk : Wv);
  __half* O = WT + blockIdx.x * (CC * FF);
  const int t = threadIdx.x;
#pragma unroll
  for (int i = 0; i < 64; ++i) {
    int idx = t + i * 256;  // input linear: c = idx>>7, f = idx&127
    sw[(idx >> 7) * 129 + (idx & 127)] = W[idx];
  }
  __syncthreads();
#pragma unroll
  for (int i = 0; i < 64; ++i) {
    int idx = t + i * 256;  // output linear: f = idx>>7, c = idx&127
    O[idx] = __float2half(sw[(idx & 127) * 129 + (idx >> 7)]);
  }
}

// ---------------------------------------------------------------------------
__device__ __forceinline__ void load_afrags(uint32_t Af[8][4], uint32_t base,
                                            int bd, int lane) {
  uint32_t ar = bd * 16 + (lane & 15);
#pragma unroll
  for (int k = 0; k < 8; ++k) {
    uint32_t fb = k * 32 + (lane >> 4) * 16;
    LDSM_X4(Af[k], base + (fb >> 7) * REG + swz(ar, fb & 127));
  }
}

__device__ __forceinline__ void gemm_16x64(float c[8][4], const uint32_t Af[8][4],
                                           uint32_t bbase, int nh, int lane) {
  uint32_t br = nh * 64 + (lane & 7);
  uint32_t cb8 = ((lane >> 3) & 3) * 16;
#pragma unroll
  for (int jq = 0; jq < 2; ++jq)
#pragma unroll
    for (int p = 0; p < 4; ++p)
#pragma unroll
      for (int jj = 0; jj < 4; ++jj) {
        int j = jq * 4 + jj;
        uint32_t r = br + j * 8;
        uint32_t fb = p * 64 + cb8;
        uint32_t bb[4];
        LDSM_X4(bb, bbase + (fb >> 7) * REG + swz(r, fb & 127));
        mma16816(c[j], Af[2 * p], bb);
        mma16816(c[j], Af[2 * p + 1], bb + 2);
      }
}

// ===========================================================================
// proj_kv: fused K = X@Wk + bk (row-major) and batch-aware VT.
// 512 threads / 16 warps: warp = (band = w>>1 in 0..7, nh = w&1).
// ===========================================================================
__global__ __launch_bounds__(512) void proj_kv(
    const float* __restrict__ X, const __half* __restrict__ WkT,
    const __half* __restrict__ WvT, const float* __restrict__ bk,
    const float* __restrict__ bv, __half* __restrict__ K, __half* __restrict__ VT) {
  extern __shared__ char sm[];
  char* sX = sm;
  char* sWk = sm + 32768;
  char* sWv = sm + 65536;
  const int t = threadIdx.x, lane = t & 31, w = t >> 5;
  const int band = w >> 1, nh = w & 1, g = lane >> 2, qd = lane & 3;
  const size_t R0 = (size_t)blockIdx.x * 128;

  stage_tile_swz<512>(WkT, CC, smem_u32(sWk), t);
  stage_tile_swz<512>(WvT, CC, smem_u32(sWv), t);
  CP_COMMIT();
  stage_x_fp16<512>(X + R0 * CC, sX, t);
  CP_WAIT0();
  __syncthreads();

  // ---- K projection: A = X rows (band), B = WkT ----
  {
    uint32_t Af[8][4];
    load_afrags(Af, smem_u32(sX), band, lane);
    float c[8][4];
#pragma unroll
    for (int j = 0; j < 8; ++j)
#pragma unroll
      for (int i = 0; i < 4; ++i) c[j][i] = 0.f;
    gemm_16x64(c, Af, smem_u32(sWk), nh, lane);

    const size_t r0 = R0 + band * 16 + g;
#pragma unroll
    for (int j = 0; j < 8; ++j) {
      int f = nh * 64 + j * 8 + qd * 2;
      float2 bv2 = *(const float2*)(bk + f);
      __half2 h0 = __floats2half2_rn(c[j][0] + bv2.x, c[j][1] + bv2.y);
      __half2 h1 = __floats2half2_rn(c[j][2] + bv2.x, c[j][3] + bv2.y);
      *(uint32_t*)(K + r0 * FF + f) = *(uint32_t*)&h0;
      *(uint32_t*)(K + (r0 + 8) * FF + f) = *(uint32_t*)&h1;
    }
  }

  // ---- VT projection: A = WvT rows (feature band), B = X rows ----
  const int bidx = (int)(R0 >> 12);
  const size_t mbase = (R0 & 4095);
  __half* VTb = VT + (size_t)bidx * FF * NKV;
  {
    uint32_t Af[8][4];
    load_afrags(Af, smem_u32(sWv), band, lane);
    float c[8][4];
#pragma unroll
    for (int j = 0; j < 8; ++j)
#pragma unroll
      for (int i = 0; i < 4; ++i) c[j][i] = 0.f;
    gemm_16x64(c, Af, smem_u32(sX), nh, lane);

    const int f0 = band * 16 + g;
    const float blo = bv[f0], bhi = bv[f0 + 8];
#pragma unroll
    for (int j = 0; j < 8; ++j) {
      size_t col = mbase + nh * 64 + j * 8 + qd * 2;
      __half2 h0 = __floats2half2_rn(c[j][0] + blo, c[j][1] + blo);
      __half2 h1 = __floats2half2_rn(c[j][2] + bhi, c[j][3] + bhi);
      *(uint32_t*)(VTb + (size_t)f0 * NKV + col) = *(uint32_t*)&h0;
      *(uint32_t*)(VTb + (size_t)(f0 + 8) * NKV + col) = *(uint32_t*)&h1;
    }
  }
}

// ===========================================================================
// Flash attention v7: v5/v6 tiling (8 warps = 4 bands x 2 kv-halves, 32q x
// 64kv warp tile) + Q PROJECTION FUSED INTO THE PROLOGUE:
// each CTA computes Q(128x128) = Xq @ WqT via HMMA; C-fragments pack
// directly into A-fragment registers (same layout trick as P).
// smem: sK[2]+sV[2] (139264) | sQX 32KB | sQW 32KB = 204800 bytes.
// ===========================================================================
__global__ __launch_bounds__(256, 1) void flash_kernel(
    const float* __restrict__ Xqg, const __half* __restrict__ WqT,
    const float* __restrict__ bq, const __half* __restrict__ Kg,
    const __half* __restrict__ VTg, float* __restrict__ Og) {
  extern __shared__ char smem[];
  char* sK[2] = {smem, smem + TILE_B};
  char* sV[2] = {smem + 2 * TILE_B, smem + 3 * TILE_B};
  char* sQX = smem + 4 * TILE_B;
  char* sQW = sQX + 32768;

  const int t = threadIdx.x, lane = t & 31, w = t >> 5;
  const int band = w >> 1, nh = w & 1;
  const int g = lane >> 2, qd = lane & 3;
  const int b = blockIdx.y, qt = blockIdx.x;

  const __half* Kb = Kg + (size_t)b * NKV * FF;
  const __half* Vb = VTg + (size_t)b * FF * NKV;

  // kick off tile-0 staging first so it overlaps the Q projection
  stage_async(Kb, FF, sK[0], t);
  stage_async(Vb, NKV, sV[0], t);
  CP_COMMIT();

  // stage Xq (fp32->fp16) and WqT for the fused Q projection
  stage_tile_swz<256>(WqT, CC, smem_u32(sQW), t);
  CP_COMMIT();
  stage_x_fp16<256>(Xqg + ((size_t)(b * NQ + qt * 128)) * CC, sQX, t);
  CP_WAIT0();
  __syncthreads();

  // ---- fused Q projection: Qf[k] A-fragments straight from HMMA C tiles ----
  uint32_t Qfu[8][4], Qfd[8][4];
#pragma unroll
  for (int half = 0; half < 2; ++half) {
    uint32_t Af[8][4];
    load_afrags(Af, smem_u32(sQX), band * 2 + half, lane);
    uint32_t(&Qf)[8][4] = half ? Qfd : Qfu;
#pragma unroll
    for (int fh = 0; fh < 2; ++fh) {
      float c[8][4];
#pragma unroll
      for (int j = 0; j < 8; ++j)
#pragma unroll
        for (int i = 0; i < 4; ++i) c[j][i] = 0.f;
      gemm_16x64(c, Af, smem_u32(sQW), fh, lane);
#pragma unroll
      for (int kk = 0; kk < 4; ++kk) {
        const int k = fh * 4 + kk;
        const int j = kk * 2;
        const int f0 = fh * 64 + j * 8 + qd * 2;
        float2 b0 = *(const float2*)(bq + f0);
        float2 b1 = *(const float2*)(bq + f0 + 8);
        __half2 lo0 = __floats2half2_rn((c[j][0] + b0.x) * QSCALE,
                                        (c[j][1] + b0.y) * QSCALE);
        __half2 hi0 = __floats2half2_rn((c[j][2] + b0.x) * QSCALE,
                                        (c[j][3] + b0.y) * QSCALE);
        __half2 lo1 = __floats2half2_rn((c[j + 1][0] + b1.x) * QSCALE,
                                        (c[j + 1][1] + b1.y) * QSCALE);
        __half2 hi1 = __floats2half2_rn((c[j + 1][2] + b1.x) * QSCALE,
                                        (c[j + 1][3] + b1.y) * QSCALE);
        Qf[k][0] = *(uint32_t*)&lo0;  // (g,      k*16+qd*2)
        Qf[k][1] = *(uint32_t*)&hi0;  // (g+8,    k*16+qd*2)
        Qf[k][2] = *(uint32_t*)&lo1;  // (g,      k*16+8+qd*2)
        Qf[k][3] = *(uint32_t*)&hi1;  // (g+8,    k*16+8+qd*2)
      }
    }
  }

  float Ou[16][4], Od[16][4];
#pragma unroll
  for (int j = 0; j < 16; ++j)
#pragma unroll
    for (int i = 0; i < 4; ++i) { Ou[j][i] = 0.f; Od[j][i] = 0.f; }
  float s0 = 0.f, s1 = 0.f, s2 = 0.f, s3 = 0.f;  // rows g, g+8, g+16, g+24

  const uint32_t lmoff = (uint32_t)(lane & 7) * TPADB + (uint32_t)(lane >> 3) * 16;
  const uint32_t khalf = (uint32_t)nh * 64 * TPADB;
  const uint32_t vcol = (uint32_t)nh * 128;

#pragma unroll 1
  for (int jt = 0; jt < NT; ++jt) {
    const int cur = jt & 1;
    if (jt + 1 < NT) {
      stage_async(Kb + (size_t)(jt + 1) * BN * FF, FF, sK[cur ^ 1], t);
      stage_async(Vb + (size_t)(jt + 1) * BN, NKV, sV[cur ^ 1], t);
      CP_COMMIT();
      CP_WAIT1();
    } else {
      CP_WAIT0();
    }
    __syncthreads();

    const uint32_t kbase = smem_u32(sK[cur]) + khalf + lmoff;
    const uint32_t vbase = smem_u32(sV[cur]) + lmoff + vcol;

#pragma unroll
    for (int jq = 0; jq < 2; ++jq) {
      const uint32_t ka = kbase + (uint32_t)jq * 4 * (8 * TPADB);

      // ---- S slice: 32 rows x 32 kv, k=128 ----
      float cu[4][4], cd[4][4];
#pragma unroll
      for (int jj = 0; jj < 4; ++jj)
#pragma unroll
        for (int i = 0; i < 4; ++i) { cu[jj][i] = 0.f; cd[jj][i] = 0.f; }
#pragma unroll
      for (int p = 0; p < 4; ++p)
#pragma unroll
        for (int jj = 0; jj < 4; ++jj) {
          uint32_t bb[4];
          LDSM_X4(bb, ka + (uint32_t)jj * (8 * TPADB) + p * 64);
          mma16816(cu[jj], Qfu[2 * p], bb);
          mma16816(cu[jj], Qfu[2 * p + 1], bb + 2);
          mma16816(cd[jj], Qfd[2 * p], bb);
          mma16816(cd[jj], Qfd[2 * p + 1], bb + 2);
        }

      // ---- exp2 + pack ----
      uint32_t Pfu[2][4], Pfd[2][4];
#pragma unroll
      for (int jj = 0; jj < 4; ++jj) {
        int kk = jj >> 1, o = (jj & 1) * 2;
        float e0 = ex2f(cu[jj][0]), e1 = ex2f(cu[jj][1]);
        float e2 = ex2f(cu[jj][2]), e3 = ex2f(cu[jj][3]);
        s0 += e0 + e1;
        s1 += e2 + e3;
        __half2 hu01 = __floats2half2_rn(e0, e1);
        __half2 hu23 = __floats2half2_rn(e2, e3);
        Pfu[kk][o] = *(uint32_t*)&hu01;
        Pfu[kk][o + 1] = *(uint32_t*)&hu23;
        float f0 = ex2f(cd[jj][0]), f1 = ex2f(cd[jj][1]);
        float f2 = ex2f(cd[jj][2]), f3 = ex2f(cd[jj][3]);
        s2 += f0 + f1;
        s3 += f2 + f3;
        __half2 hd01 = __floats2half2_rn(f0, f1);
        __half2 hd23 = __floats2half2_rn(f2, f3);
        Pfd[kk][o] = *(uint32_t*)&hd01;
        Pfd[kk][o + 1] = *(uint32_t*)&hd23;
      }

      // ---- PV slice: k = 32 kv, all 128 features ----
#pragma unroll
      for (int j = 0; j < 16; ++j) {
        uint32_t bb[4];
        LDSM_X4(bb, vbase + (uint32_t)j * (8 * TPADB) + jq * 64);
        mma16816(Ou[j], Pfu[0], bb);
        mma16816(Ou[j], Pfu[1], bb + 2);
        mma16816(Od[j], Pfd[0], bb);
        mma16816(Od[j], Pfd[1], bb + 2);
      }
    }
    __syncthreads();
  }

  // ---- reduce row sums within quads ----
  s0 += __shfl_xor_sync(0xffffffffu, s0, 1);
  s0 += __shfl_xor_sync(0xffffffffu, s0, 2);
  s1 += __shfl_xor_sync(0xffffffffu, s1, 1);
  s1 += __shfl_xor_sync(0xffffffffu, s1, 2);
  s2 += __shfl_xor_sync(0xffffffffu, s2, 1);
  s2 += __shfl_xor_sync(0xffffffffu, s2, 2);
  s3 += __shfl_xor_sync(0xffffffffu, s3, 1);
  s3 += __shfl_xor_sync(0xffffffffu, s3, 2);

  // ---- combine kv-halves: nh1 dumps O + l to smem, nh0 adds + writes ----
  float* sO = (float*)smem;                          // 4 bands x 32 rows x OPITCH
  float* sL = (float*)(smem + 4 * 32 * OPITCH * 4);  // 4 bands x 32 rows
  if (nh == 1) {
    float* dst = sO + band * 32 * OPITCH;
#pragma unroll
    for (int j = 0; j < 16; ++j) {
      int f = j * 8 + qd * 2;
      *(float2*)(dst + g * OPITCH + f) = make_float2(Ou[j][0], Ou[j][1]);
      *(float2*)(dst + (g + 8) * OPITCH + f) = make_float2(Ou[j][2], Ou[j][3]);
      *(float2*)(dst + (g + 16) * OPITCH + f) = make_float2(Od[j][0], Od[j][1]);
      *(float2*)(dst + (g + 24) * OPITCH + f) = make_float2(Od[j][2], Od[j][3]);
    }
    if (qd == 0) {
      float* lb = sL + band * 32;
      lb[g] = s0;
      lb[g + 8] = s1;
      lb[g + 16] = s2;
      lb[g + 24] = s3;
    }
  }
  __syncthreads();
  if (nh == 0) {
    const float* src = sO + band * 32 * OPITCH;
    const float* lb = sL + band * 32;
    const float r0 = 1.0f / (s0 + lb[g]);
    const float r1 = 1.0f / (s1 + lb[g + 8]);
    const float r2 = 1.0f / (s2 + lb[g + 16]);
    const float r3 = 1.0f / (s3 + lb[g + 24]);
    float* Ob = Og + ((size_t)(b * NQ + qt * 128 + band * 32)) * FF;
#pragma unroll
    for (int j = 0; j < 16; ++j) {
      int f = j * 8 + qd * 2;
      float2 a0 = *(const float2*)(src + g * OPITCH + f);
      float2 a1 = *(const float2*)(src + (g + 8) * OPITCH + f);
      float2 a2 = *(const float2*)(src + (g + 16) * OPITCH + f);
      float2 a3 = *(const float2*)(src + (g + 24) * OPITCH + f);
      *(float2*)(Ob + (size_t)g * FF + f) =
          make_float2((Ou[j][0] + a0.x) * r0, (Ou[j][1] + a0.y) * r0);
      *(float2*)(Ob + (size_t)(g + 8) * FF + f) =
          make_float2((Ou[j][2] + a1.x) * r1, (Ou[j][3] + a1.y) * r1);
      *(float2*)(Ob + (size_t)(g + 16) * FF + f) =
          make_float2((Od[j][0] + a2.x) * r2, (Od[j][1] + a2.y) * r2);
      *(float2*)(Ob + (size_t)(g + 24) * FF + f) =
          make_float2((Od[j][2] + a3.x) * r3, (Od[j][3] + a3.y) * r3);
    }
  }
}

// ===========================================================================
extern "C" void kernel_launch(void* const* d_in, const int* in_sizes, int n_in,
                              void* d_out, int out_size) {
  const float* qin  = (const float*)d_in[0];
  const float* kvin = (const float*)d_in[1];
  const float* Wq   = (const float*)d_in[2];
  const float* bq   = (const float*)d_in[3];
  const float* Wk   = (const float*)d_in[4];
  const float* bk   = (const float*)d_in[5];
  const float* Wv   = (const float*)d_in[6];
  const float* bv   = (const float*)d_in[7];
  float* out = (float*)d_out;

  __half *dK, *dVT, *dWT;
  cudaGetSymbolAddress((void**)&dK, g_K);
  cudaGetSymbolAddress((void**)&dVT, g_VT);
  cudaGetSymbolAddress((void**)&dWT, g_WT);

  const int smprep = 128 * 129 * 4;          // 66048
  const int smkv = 3 * 32768;                // 98304
  const int smf = 4 * TILE_B + 2 * 32768;    // 204800
  cudaFuncSetAttribute(prep_wt, cudaFuncAttributeMaxDynamicSharedMemorySize, smprep);
  cudaFuncSetAttribute(proj_kv, cudaFuncAttributeMaxDynamicSharedMemorySize, smkv);
  cudaFuncSetAttribute(flash_kernel, cudaFuncAttributeMaxDynamicSharedMemorySize, smf);

  prep_wt<<<3, 256, smprep>>>(Wq, Wk, Wv, dWT);
  proj_kv<<<BB * NKV / 128, 512, smkv>>>(kvin, dWT + CC * FF, dWT + 2 * CC * FF,
                                         bk, bv, dK, dVT);

  dim3 fg(NQ / 128, BB);
  flash_kernel<<<fg, 256, smf>>>(qin, dWT, bq, dK, dVT, out);
}